// round 11
// baseline (speedup 1.0000x reference)
#include <cuda_runtime.h>
#include <math.h>
#include <stdint.h>

// ---------------- problem constants ----------------
constexpr int S     = 4096;
constexpr int N_KV  = 2048;
constexpr int N_AUX = 512;
constexpr int N_NEW = 1536;
constexpr int H     = 2048;
constexpr int NH    = 16;
constexpr int HD    = 128;
constexpr int FF    = 8192;
constexpr int NQ    = N_NEW + N_AUX;   // 2048
constexpr int NK    = N_KV + NQ;       // 4096
constexpr int PRUNE_KN = 409;
constexpr float EPSF = 1e-6f;

// ---------------- output packing (tuple flattened in order) ----------------
constexpr size_t SZ_OUT = (size_t)NQ * H;          // 4,194,304
constexpr size_t SZ_KC  = (size_t)NH * S * HD;     // 8,388,608
constexpr size_t SZ_AUX = (size_t)S * H;           // 8,388,608
constexpr size_t OFF_OUT = 0;
constexpr size_t OFF_KC  = OFF_OUT + SZ_OUT;
constexpr size_t OFF_VC  = OFF_KC + SZ_KC;
constexpr size_t OFF_AUX = OFF_VC + SZ_KC;

// ---------------- scratch (static device memory; no runtime allocs) ----------------
__device__ float g_hs  [(size_t)NQ * H];
__device__ float g_x   [(size_t)NQ * H];      // ln1 output, reused as ln2 output
__device__ float g_lin [(size_t)NQ * H];      // q/k/v linear (sequential reuse)
__device__ float g_qh  [(size_t)NH * NQ * HD];
__device__ float g_kall[(size_t)NH * NK * HD];
__device__ float g_vall[(size_t)NH * NK * HD];
__device__ float g_attn[(size_t)NH * NQ * NK]; // 537 MB
__device__ float g_ctx [(size_t)NQ * H];
__device__ float g_hs2 [(size_t)NQ * H];
__device__ float g_gate[(size_t)NQ * FF];
__device__ float g_up  [(size_t)NQ * FF];
__device__ int   g_hsidx[NQ];
__device__ int   g_qpos [NQ];
__device__ int   g_keytok[NK];
__device__ int   g_kpos [NK];
__device__ int   g_map  [S];
__device__ int   g_auxbits[S];
__device__ int   g_pruneflag[S];

// ---------------- index / gather kernels ----------------
__global__ void k_build_idx(const int* __restrict__ kv_idxs,
                            const int* __restrict__ aux_idxs,
                            const int* __restrict__ new_idxs,
                            const int* __restrict__ positions) {
    int i = blockIdx.x * blockDim.x + threadIdx.x;
    if (i < S) { g_map[i] = 0; g_auxbits[i] = 0; g_pruneflag[i] = 0; }
    if (i < NQ) {
        int t = (i < N_NEW) ? new_idxs[i] : aux_idxs[i - N_NEW];
        g_hsidx[i] = t;
        g_qpos[i]  = positions[t];
    }
    if (i < NK) {
        int t;
        if (i < N_KV) t = kv_idxs[i];
        else {
            int j = i - N_KV;
            t = (j < N_NEW) ? new_idxs[j] : aux_idxs[j - N_NEW];
        }
        g_keytok[i] = t;
        g_kpos[i]   = positions[t];
    }
}

__global__ void k_scatter_idx(const int* __restrict__ aux_idxs) {
    int i = blockIdx.x * blockDim.x + threadIdx.x;
    if (i < NQ)   g_map[g_hsidx[i]] = i;
    if (i < N_AUX) g_auxbits[aux_idxs[i]] = 1;
}

__global__ void k_gather_hs(const float* __restrict__ hidden,
                            const float* __restrict__ aux_cache) {
    int i4 = blockIdx.x * blockDim.x + threadIdx.x;   // over NQ*H/4
    if (i4 >= NQ * (H / 4)) return;
    int n  = i4 / (H / 4);
    int c4 = i4 % (H / 4);
    float4 v;
    if (n < N_NEW) v = ((const float4*)hidden)[(size_t)n * (H / 4) + c4];
    else {
        int r = g_hsidx[n];  // == aux_idxs[n - N_NEW]
        v = ((const float4*)aux_cache)[(size_t)r * (H / 4) + c4];
    }
    ((float4*)g_hs)[i4] = v;
}

__global__ void k_copy4(const float4* __restrict__ src, float4* __restrict__ dst, int n4) {
    int i = blockIdx.x * blockDim.x + threadIdx.x;
    if (i < n4) dst[i] = src[i];
}

// ---------------- block reduction helpers (blockDim.x == 256) ----------------
__device__ __forceinline__ float blockSum256(float v, float* sh8) {
    int lane = threadIdx.x & 31, w = threadIdx.x >> 5;
#pragma unroll
    for (int o = 16; o; o >>= 1) v += __shfl_xor_sync(0xffffffffu, v, o);
    if (lane == 0) sh8[w] = v;
    __syncthreads();
    float r = 0.f;
#pragma unroll
    for (int i = 0; i < 8; i++) r += sh8[i];
    __syncthreads();
    return r;
}
__device__ __forceinline__ float blockMax256(float v, float* sh8) {
    int lane = threadIdx.x & 31, w = threadIdx.x >> 5;
#pragma unroll
    for (int o = 16; o; o >>= 1) v = fmaxf(v, __shfl_xor_sync(0xffffffffu, v, o));
    if (lane == 0) sh8[w] = v;
    __syncthreads();
    float r = -3.4e38f;
#pragma unroll
    for (int i = 0; i < 8; i++) r = fmaxf(r, sh8[i]);
    __syncthreads();
    return r;
}

// ---------------- RMSNorm (one block per row, 256 threads) ----------------
__global__ void k_rmsnorm(const float* __restrict__ in, float* __restrict__ outp,
                          const float* __restrict__ w) {
    __shared__ float sh8[8];
    int n = blockIdx.x;
    const float* r = in + (size_t)n * H;
    float s = 0.f;
#pragma unroll
    for (int i = 0; i < H / 256; i++) {
        float v = r[i * 256 + threadIdx.x];
        s += v * v;
    }
    float tot = blockSum256(s, sh8);
    float mean = tot / (float)H;
    float scale = (float)(1.0 / sqrt((double)mean + (double)EPSF));
    float* o = outp + (size_t)n * H;
#pragma unroll
    for (int i = 0; i < H / 256; i++) {
        int c = i * 256 + threadIdx.x;
        o[c] = (r[c] * scale) * w[c];
    }
}

// ---------------- SGEMM: C = alpha*A*B(^T) (+ resid), 128x128x8, 256 thr ----------------
template <bool TRANS_B, bool ADD_RESID>
__launch_bounds__(256, 2)
__global__ void sgemm128(const float* __restrict__ A, const float* __restrict__ B,
                         float* __restrict__ C, const float* __restrict__ R,
                         int K, int lda, int ldb, int ldc, float alpha,
                         long long sA, long long sB, long long sC) {
    constexpr int BK = 8;
    __shared__ float As[BK][128];
    __shared__ float Bs[BK][128];
    const int b = blockIdx.z;
    A += (size_t)b * sA;
    B += (size_t)b * sB;
    C += (size_t)b * sC;
    const int tid  = threadIdx.x;
    const int row0 = blockIdx.y * 128;
    const int col0 = blockIdx.x * 128;

    const int arow = tid >> 1, acol = (tid & 1) * 4;
    int brow, bcol;
    if (TRANS_B) { brow = tid >> 1; bcol = (tid & 1) * 4; }
    else         { brow = tid >> 5; bcol = (tid & 31) * 4; }

    const int tx = (tid & 15) * 8;
    const int ty = (tid >> 4) * 8;

    float acc[8][8];
#pragma unroll
    for (int i = 0; i < 8; i++)
#pragma unroll
        for (int j = 0; j < 8; j++) acc[i][j] = 0.f;

    for (int k0 = 0; k0 < K; k0 += BK) {
        float4 av = *(const float4*)&A[(size_t)(row0 + arow) * lda + k0 + acol];
        As[acol + 0][arow] = av.x;
        As[acol + 1][arow] = av.y;
        As[acol + 2][arow] = av.z;
        As[acol + 3][arow] = av.w;
        if (TRANS_B) {
            float4 bv = *(const float4*)&B[(size_t)(col0 + brow) * ldb + k0 + bcol];
            Bs[bcol + 0][brow] = bv.x;
            Bs[bcol + 1][brow] = bv.y;
            Bs[bcol + 2][brow] = bv.z;
            Bs[bcol + 3][brow] = bv.w;
        } else {
            float4 bv = *(const float4*)&B[(size_t)(k0 + brow) * ldb + col0 + bcol];
            *(float4*)&Bs[brow][bcol] = bv;
        }
        __syncthreads();
#pragma unroll
        for (int kk = 0; kk < BK; kk++) {
            float a[8], bb[8];
            *(float4*)&a[0]  = *(const float4*)&As[kk][ty];
            *(float4*)&a[4]  = *(const float4*)&As[kk][ty + 4];
            *(float4*)&bb[0] = *(const float4*)&Bs[kk][tx];
            *(float4*)&bb[4] = *(const float4*)&Bs[kk][tx + 4];
#pragma unroll
            for (int i = 0; i < 8; i++)
#pragma unroll
                for (int j = 0; j < 8; j++)
                    acc[i][j] = fmaf(a[i], bb[j], acc[i][j]);
        }
        __syncthreads();
    }
#pragma unroll
    for (int i = 0; i < 8; i++) {
        size_t roff = (size_t)(row0 + ty + i) * ldc + col0 + tx;
#pragma unroll
        for (int j = 0; j < 8; j += 4) {
            float4 o;
            o.x = alpha * acc[i][j + 0];
            o.y = alpha * acc[i][j + 1];
            o.z = alpha * acc[i][j + 2];
            o.w = alpha * acc[i][j + 3];
            if (ADD_RESID) {
                float4 rr = *(const float4*)&R[roff + j];
                o.x += rr.x; o.y += rr.y; o.z += rr.z; o.w += rr.w;
            }
            *(float4*)&C[roff + j] = o;
        }
    }
}

// ---------------- RoPE (replicates reference fp32 rounding chain) ----------------
__device__ __forceinline__ void rope_cs(int pos, int j, float& c, float& s) {
    double e  = (double)(2 * j) / (double)HD;
    float  pf = (float)pow(10000.0, e);   // correctly rounded f32 of theta^e
    float  inv = 1.0f / pf;               // f32 division like reference
    float  f = (float)pos * inv;          // single f32 rounding like reference
    c = (float)cos((double)f);
    s = (float)sin((double)f);
}

__global__ void k_rope_q() {
    int n = blockIdx.x, h = blockIdx.y, j = threadIdx.x;  // j in [0,64)
    float c, s;
    rope_cs(g_qpos[n], j, c, s);
    const float* src = g_lin + (size_t)n * H + h * HD;
    float x0 = src[j], x1 = src[j + 64];
    float* dst = g_qh + ((size_t)h * NQ + n) * HD;
    dst[j]      = x0 * c - x1 * s;
    dst[j + 64] = x1 * c + x0 * s;
}

__global__ void k_rope_k(float* __restrict__ outbuf) {
    int n = blockIdx.x, h = blockIdx.y, j = threadIdx.x;
    float c, s;
    rope_cs(g_qpos[n], j, c, s);
    const float* src = g_lin + (size_t)n * H + h * HD;
    float x0 = src[j], x1 = src[j + 64];
    float o0 = x0 * c - x1 * s;
    float o1 = x1 * c + x0 * s;
    float* dst = g_kall + ((size_t)h * NK + N_KV + n) * HD;
    dst[j] = o0; dst[j + 64] = o1;
    float* kc = outbuf + OFF_KC + ((size_t)h * S + g_hsidx[n]) * HD;
    kc[j] = o0; kc[j + 64] = o1;
}

__global__ void k_transpose_v(float* __restrict__ outbuf) {
    int n = blockIdx.x, h = blockIdx.y, d = threadIdx.x;  // d in [0,128)
    float val = g_lin[(size_t)n * H + h * HD + d];
    g_vall[((size_t)h * NK + N_KV + n) * HD + d] = val;
    outbuf[OFF_VC + ((size_t)h * S + g_hsidx[n]) * HD + d] = val;
}

__global__ void k_gather_kv(const float* __restrict__ key_cache,
                            const float* __restrict__ value_cache) {
    int kk = blockIdx.x, h = blockIdx.y, d = threadIdx.x;
    int tok = g_keytok[kk];  // kk < N_KV -> kv_idxs[kk]
    g_kall[((size_t)h * NK + kk) * HD + d] = key_cache[((size_t)h * S + tok) * HD + d];
    g_vall[((size_t)h * NK + kk) * HD + d] = value_cache[((size_t)h * S + tok) * HD + d];
}

// ---------------- masked softmax over NK (one block per (q,h)) ----------------
__global__ void k_softmax() {
    __shared__ float sh8[8];
    const int q = blockIdx.x, h = blockIdx.y;
    float* row = g_attn + ((size_t)h * NQ + q) * (size_t)NK;
    const int qp = g_qpos[q];
    const int t = threadIdx.x;
    float v[NK / 256];
    float mx = -3.4e38f;
#pragma unroll
    for (int i = 0; i < NK / 256; i++) {
        int k = i * 256 + t;
        float sc = row[k];
        if (g_kpos[k] > qp) sc += -1e9f;
        v[i] = sc;
        mx = fmaxf(mx, sc);
    }
    mx = blockMax256(mx, sh8);
    float sum = 0.f;
#pragma unroll
    for (int i = 0; i < NK / 256; i++) {
        v[i] = expf(v[i] - mx);
        sum += v[i];
    }
    sum = blockSum256(sum, sh8);
#pragma unroll
    for (int i = 0; i < NK / 256; i++) row[i * 256 + t] = v[i] / sum;
}

// ---------------- SiLU(gate) * up, in place into g_up ----------------
__global__ void k_silu(size_t n) {
    size_t i = (size_t)blockIdx.x * blockDim.x + threadIdx.x;
    if (i >= n) return;
    float x = g_gate[i];
    float sig = 1.0f / (1.0f + expf(-x));
    g_up[i] = (x * sig) * g_up[i];
}

// ---------------- prune selection ----------------
// Reference semantics decoded (validated by round-5/6 error magnitudes):
//   imp = jnp.take(attn, last_key, axis=2): last_key = N_KV+last_hs >= 2048 is
//   OOB on the Q axis (size NQ=2048) -> jnp default 'fill' mode -> imp = +NaN
//   everywhere. Then imp.at[last_key].set(inf) (in bounds on [NK]) -> one +inf.
//   -imp: +NaN negates to -NaN; the +inf becomes -inf. XLA top_k total order:
//   -NaN < -inf < finite < +inf < +NaN, so the single -inf at last_key is the
//   LARGEST element and NaNs tie stably by index. Hence
//     prune_list = [last_key, 0, 1, ..., 407]
//     to_prune_tok = {S-1} U kv_idxs[0..407]
__global__ void k_prune() {
    int i = blockIdx.x * blockDim.x + threadIdx.x;
    if (i == 0) {
        // token S-1 is always a new-idx token, never in aux_idxs
        g_pruneflag[S - 1] = 1;
    }
    if (i >= PRUNE_KN - 1) return;   // first 408 keys
    int tok = g_keytok[i];           // i < 408 < N_KV -> kv_idxs[i]
    if (!g_auxbits[tok]) g_pruneflag[tok] = 1;
}

// ---------------- aux cache scatter: aux[t] = out[map_full[t]] ----------------
__global__ void k_aux_scatter(float* __restrict__ outbuf) {
    int tpos = blockIdx.x;
    if (!g_pruneflag[tpos]) return;
    int src = g_map[tpos];   // 0 for tokens not in hs_idxs (matches reference map_full)
    const float4* s = (const float4*)(outbuf + OFF_OUT + (size_t)src * H);
    float4* d = (float4*)(outbuf + OFF_AUX + (size_t)tpos * H);
    for (int c = threadIdx.x; c < H / 4; c += blockDim.x) d[c] = s[c];
}

// ---------------- launch ----------------
extern "C" void kernel_launch(void* const* d_in, const int* in_sizes, int n_in,
                              void* d_out, int out_size) {
    (void)in_sizes; (void)n_in; (void)out_size;
    const float* hidden      = (const float*)d_in[0];
    const float* key_cache   = (const float*)d_in[1];
    const float* value_cache = (const float*)d_in[2];
    const float* aux_cache   = (const float*)d_in[3];
    const int*   kv_idxs     = (const int*)d_in[4];
    const int*   aux_idxs    = (const int*)d_in[5];
    const int*   new_idxs    = (const int*)d_in[6];
    const int*   positions   = (const int*)d_in[7];
    const float* wq     = (const float*)d_in[8];
    const float* wk     = (const float*)d_in[9];
    const float* wv     = (const float*)d_in[10];
    const float* wo     = (const float*)d_in[11];
    const float* wgate  = (const float*)d_in[12];
    const float* wup    = (const float*)d_in[13];
    const float* wdown  = (const float*)d_in[14];
    const float* ln1    = (const float*)d_in[15];
    const float* ln2    = (const float*)d_in[16];
    float* out = (float*)d_out;

    float *hs, *x, *lin, *qh, *kall, *vall, *attn, *ctx, *hs2, *gate, *up;
    cudaGetSymbolAddress((void**)&hs,   g_hs);
    cudaGetSymbolAddress((void**)&x,    g_x);
    cudaGetSymbolAddress((void**)&lin,  g_lin);
    cudaGetSymbolAddress((void**)&qh,   g_qh);
    cudaGetSymbolAddress((void**)&kall, g_kall);
    cudaGetSymbolAddress((void**)&vall, g_vall);
    cudaGetSymbolAddress((void**)&attn, g_attn);
    cudaGetSymbolAddress((void**)&ctx,  g_ctx);
    cudaGetSymbolAddress((void**)&hs2,  g_hs2);
    cudaGetSymbolAddress((void**)&gate, g_gate);
    cudaGetSymbolAddress((void**)&up,   g_up);

    const float ALPHA = 1.0f / sqrtf((float)HD);

    // indices + gathers + base copies of the three cache outputs
    k_build_idx<<<(S + 255) / 256, 256>>>(kv_idxs, aux_idxs, new_idxs, positions);
    k_scatter_idx<<<(NQ + 255) / 256, 256>>>(aux_idxs);
    k_gather_hs<<<(NQ * (H / 4) + 255) / 256, 256>>>(hidden, aux_cache);
    k_copy4<<<(int)((SZ_KC / 4 + 255) / 256), 256>>>((const float4*)key_cache,   (float4*)(out + OFF_KC), (int)(SZ_KC / 4));
    k_copy4<<<(int)((SZ_KC / 4 + 255) / 256), 256>>>((const float4*)value_cache, (float4*)(out + OFF_VC), (int)(SZ_KC / 4));
    k_copy4<<<(int)((SZ_AUX / 4 + 255) / 256), 256>>>((const float4*)aux_cache,  (float4*)(out + OFF_AUX), (int)(SZ_AUX / 4));

    // ln1
    k_rmsnorm<<<NQ, 256>>>(hs, x, ln1);

    // QKV projections (+ RoPE / transpose / cache scatter)
    sgemm128<false, false><<<dim3(H / 128, NQ / 128, 1), 256>>>(x, wq, lin, nullptr, H, H, H, H, 1.f, 0, 0, 0);
    k_rope_q<<<dim3(NQ, NH), 64>>>();
    sgemm128<false, false><<<dim3(H / 128, NQ / 128, 1), 256>>>(x, wk, lin, nullptr, H, H, H, H, 1.f, 0, 0, 0);
    k_rope_k<<<dim3(NQ, NH), 64>>>(out);
    sgemm128<false, false><<<dim3(H / 128, NQ / 128, 1), 256>>>(x, wv, lin, nullptr, H, H, H, H, 1.f, 0, 0, 0);
    k_transpose_v<<<dim3(NQ, NH), HD>>>(out);
    k_gather_kv<<<dim3(N_KV, NH), HD>>>(key_cache, value_cache);

    // attention
    sgemm128<true, false><<<dim3(NK / 128, NQ / 128, NH), 256>>>(
        qh, kall, attn, nullptr, HD, HD, HD, NK, ALPHA,
        (long long)NQ * HD, (long long)NK * HD, (long long)NQ * NK);
    k_softmax<<<dim3(NQ, NH), 256>>>();
    sgemm128<false, false><<<dim3(HD / 128, NQ / 128, NH), 256>>>(
        attn, vall, ctx, nullptr, NK, NK, HD, H, 1.f,
        (long long)NQ * NK, (long long)NK * HD, (long long)HD);

    // O-proj + residual -> hs2
    sgemm128<false, true><<<dim3(H / 128, NQ / 128, 1), 256>>>(ctx, wo, hs2, hs, H, H, H, H, 1.f, 0, 0, 0);

    // FFN
    k_rmsnorm<<<NQ, 256>>>(hs2, x, ln2);
    sgemm128<false, false><<<dim3(FF / 128, NQ / 128, 1), 256>>>(x, wgate, gate, nullptr, H, H, FF, FF, 1.f, 0, 0, 0);
    sgemm128<false, false><<<dim3(FF / 128, NQ / 128, 1), 256>>>(x, wup, up, nullptr, H, H, FF, FF, 1.f, 0, 0, 0);
    k_silu<<<(int)(((size_t)NQ * FF + 255) / 256), 256>>>((size_t)NQ * FF);
    sgemm128<false, true><<<dim3(H / 128, NQ / 128, 1), 256>>>(up, wdown, out + OFF_OUT, hs2, FF, FF, H, H, 1.f, 0, 0, 0);

    // prune selection + aux scatter (needs final out rows)
    k_prune<<<(PRUNE_KN + 255) / 256, 256>>>();
    k_aux_scatter<<<S, 256>>>(out);
}

// round 12
// speedup vs baseline: 1.0010x; 1.0010x over previous
#include <cuda_runtime.h>
#include <math.h>
#include <stdint.h>

// ---------------- problem constants ----------------
constexpr int S     = 4096;
constexpr int N_KV  = 2048;
constexpr int N_AUX = 512;
constexpr int N_NEW = 1536;
constexpr int H     = 2048;
constexpr int NH    = 16;
constexpr int HD    = 128;
constexpr int FF    = 8192;
constexpr int NQ    = N_NEW + N_AUX;   // 2048
constexpr int NK    = N_KV + NQ;       // 4096
constexpr int PRUNE_KN = 409;
constexpr float EPSF = 1e-6f;

// ---------------- output packing (tuple flattened in order) ----------------
constexpr size_t SZ_OUT = (size_t)NQ * H;          // 4,194,304
constexpr size_t SZ_KC  = (size_t)NH * S * HD;     // 8,388,608
constexpr size_t SZ_AUX = (size_t)S * H;           // 8,388,608
constexpr size_t OFF_OUT = 0;
constexpr size_t OFF_KC  = OFF_OUT + SZ_OUT;
constexpr size_t OFF_VC  = OFF_KC + SZ_KC;
constexpr size_t OFF_AUX = OFF_VC + SZ_KC;

// ---------------- scratch (static device memory; no runtime allocs) ----------------
__device__ float g_hs  [(size_t)NQ * H];
__device__ float g_x   [(size_t)NQ * H];      // ln1 output, reused as ln2 output
__device__ float g_lin [(size_t)NQ * H];      // q/k/v linear (sequential reuse)
__device__ float g_qh  [(size_t)NH * NQ * HD];
__device__ float g_kall[(size_t)NH * NK * HD];
__device__ float g_vall[(size_t)NH * NK * HD];
__device__ float g_attn[(size_t)NH * NQ * NK]; // 537 MB
__device__ float g_ctx [(size_t)NQ * H];
__device__ float g_hs2 [(size_t)NQ * H];
__device__ float g_gate[(size_t)NQ * FF];
__device__ float g_up  [(size_t)NQ * FF];
__device__ int   g_hsidx[NQ];
__device__ int   g_qpos [NQ];
__device__ int   g_keytok[NK];
__device__ int   g_kpos [NK];
__device__ int   g_map  [S];
__device__ int   g_auxbits[S];
__device__ int   g_pruneflag[S];

// ---------------- index / gather kernels ----------------
__global__ void k_build_idx(const int* __restrict__ kv_idxs,
                            const int* __restrict__ aux_idxs,
                            const int* __restrict__ new_idxs,
                            const int* __restrict__ positions) {
    int i = blockIdx.x * blockDim.x + threadIdx.x;
    if (i < S) { g_map[i] = 0; g_auxbits[i] = 0; g_pruneflag[i] = 0; }
    if (i < NQ) {
        int t = (i < N_NEW) ? new_idxs[i] : aux_idxs[i - N_NEW];
        g_hsidx[i] = t;
        g_qpos[i]  = positions[t];
    }
    if (i < NK) {
        int t;
        if (i < N_KV) t = kv_idxs[i];
        else {
            int j = i - N_KV;
            t = (j < N_NEW) ? new_idxs[j] : aux_idxs[j - N_NEW];
        }
        g_keytok[i] = t;
        g_kpos[i]   = positions[t];
    }
}

__global__ void k_scatter_idx(const int* __restrict__ aux_idxs) {
    int i = blockIdx.x * blockDim.x + threadIdx.x;
    if (i < NQ)   g_map[g_hsidx[i]] = i;
    if (i < N_AUX) g_auxbits[aux_idxs[i]] = 1;
}

__global__ void k_gather_hs(const float* __restrict__ hidden,
                            const float* __restrict__ aux_cache) {
    int i4 = blockIdx.x * blockDim.x + threadIdx.x;   // over NQ*H/4
    if (i4 >= NQ * (H / 4)) return;
    int n  = i4 / (H / 4);
    int c4 = i4 % (H / 4);
    float4 v;
    if (n < N_NEW) v = ((const float4*)hidden)[(size_t)n * (H / 4) + c4];
    else {
        int r = g_hsidx[n];  // == aux_idxs[n - N_NEW]
        v = ((const float4*)aux_cache)[(size_t)r * (H / 4) + c4];
    }
    ((float4*)g_hs)[i4] = v;
}

__global__ void k_copy4(const float4* __restrict__ src, float4* __restrict__ dst, int n4) {
    int i = blockIdx.x * blockDim.x + threadIdx.x;
    if (i < n4) dst[i] = src[i];
}

// ---------------- block reduction helpers (blockDim.x == 256) ----------------
__device__ __forceinline__ float blockSum256(float v, float* sh8) {
    int lane = threadIdx.x & 31, w = threadIdx.x >> 5;
#pragma unroll
    for (int o = 16; o; o >>= 1) v += __shfl_xor_sync(0xffffffffu, v, o);
    if (lane == 0) sh8[w] = v;
    __syncthreads();
    float r = 0.f;
#pragma unroll
    for (int i = 0; i < 8; i++) r += sh8[i];
    __syncthreads();
    return r;
}
__device__ __forceinline__ float blockMax256(float v, float* sh8) {
    int lane = threadIdx.x & 31, w = threadIdx.x >> 5;
#pragma unroll
    for (int o = 16; o; o >>= 1) v = fmaxf(v, __shfl_xor_sync(0xffffffffu, v, o));
    if (lane == 0) sh8[w] = v;
    __syncthreads();
    float r = -3.4e38f;
#pragma unroll
    for (int i = 0; i < 8; i++) r = fmaxf(r, sh8[i]);
    __syncthreads();
    return r;
}

// ---------------- RMSNorm (one block per row, 256 threads) ----------------
__global__ void k_rmsnorm(const float* __restrict__ in, float* __restrict__ outp,
                          const float* __restrict__ w) {
    __shared__ float sh8[8];
    int n = blockIdx.x;
    const float* r = in + (size_t)n * H;
    float s = 0.f;
#pragma unroll
    for (int i = 0; i < H / 256; i++) {
        float v = r[i * 256 + threadIdx.x];
        s += v * v;
    }
    float tot = blockSum256(s, sh8);
    float mean = tot / (float)H;
    float scale = (float)(1.0 / sqrt((double)mean + (double)EPSF));
    float* o = outp + (size_t)n * H;
#pragma unroll
    for (int i = 0; i < H / 256; i++) {
        int c = i * 256 + threadIdx.x;
        o[c] = (r[c] * scale) * w[c];
    }
}

// ---------------- SGEMM: C = alpha*A*B(^T) (+ resid), 128x128x8, 256 thr ----------------
template <bool TRANS_B, bool ADD_RESID>
__launch_bounds__(256, 2)
__global__ void sgemm128(const float* __restrict__ A, const float* __restrict__ B,
                         float* __restrict__ C, const float* __restrict__ R,
                         int K, int lda, int ldb, int ldc, float alpha,
                         long long sA, long long sB, long long sC) {
    constexpr int BK = 8;
    __shared__ float As[BK][128];
    __shared__ float Bs[BK][128];
    const int b = blockIdx.z;
    A += (size_t)b * sA;
    B += (size_t)b * sB;
    C += (size_t)b * sC;
    const int tid  = threadIdx.x;
    const int row0 = blockIdx.y * 128;
    const int col0 = blockIdx.x * 128;

    const int arow = tid >> 1, acol = (tid & 1) * 4;
    int brow, bcol;
    if (TRANS_B) { brow = tid >> 1; bcol = (tid & 1) * 4; }
    else         { brow = tid >> 5; bcol = (tid & 31) * 4; }

    const int tx = (tid & 15) * 8;
    const int ty = (tid >> 4) * 8;

    float acc[8][8];
#pragma unroll
    for (int i = 0; i < 8; i++)
#pragma unroll
        for (int j = 0; j < 8; j++) acc[i][j] = 0.f;

    for (int k0 = 0; k0 < K; k0 += BK) {
        float4 av = *(const float4*)&A[(size_t)(row0 + arow) * lda + k0 + acol];
        As[acol + 0][arow] = av.x;
        As[acol + 1][arow] = av.y;
        As[acol + 2][arow] = av.z;
        As[acol + 3][arow] = av.w;
        if (TRANS_B) {
            float4 bv = *(const float4*)&B[(size_t)(col0 + brow) * ldb + k0 + bcol];
            Bs[bcol + 0][brow] = bv.x;
            Bs[bcol + 1][brow] = bv.y;
            Bs[bcol + 2][brow] = bv.z;
            Bs[bcol + 3][brow] = bv.w;
        } else {
            float4 bv = *(const float4*)&B[(size_t)(k0 + brow) * ldb + col0 + bcol];
            *(float4*)&Bs[brow][bcol] = bv;
        }
        __syncthreads();
#pragma unroll
        for (int kk = 0; kk < BK; kk++) {
            float a[8], bb[8];
            *(float4*)&a[0]  = *(const float4*)&As[kk][ty];
            *(float4*)&a[4]  = *(const float4*)&As[kk][ty + 4];
            *(float4*)&bb[0] = *(const float4*)&Bs[kk][tx];
            *(float4*)&bb[4] = *(const float4*)&Bs[kk][tx + 4];
#pragma unroll
            for (int i = 0; i < 8; i++)
#pragma unroll
                for (int j = 0; j < 8; j++)
                    acc[i][j] = fmaf(a[i], bb[j], acc[i][j]);
        }
        __syncthreads();
    }
#pragma unroll
    for (int i = 0; i < 8; i++) {
        size_t roff = (size_t)(row0 + ty + i) * ldc + col0 + tx;
#pragma unroll
        for (int j = 0; j < 8; j += 4) {
            float4 o;
            o.x = alpha * acc[i][j + 0];
            o.y = alpha * acc[i][j + 1];
            o.z = alpha * acc[i][j + 2];
            o.w = alpha * acc[i][j + 3];
            if (ADD_RESID) {
                float4 rr = *(const float4*)&R[roff + j];
                o.x += rr.x; o.y += rr.y; o.z += rr.z; o.w += rr.w;
            }
            *(float4*)&C[roff + j] = o;
        }
    }
}

// ---------------- RoPE (replicates reference fp32 rounding chain) ----------------
__device__ __forceinline__ void rope_cs(int pos, int j, float& c, float& s) {
    double e  = (double)(2 * j) / (double)HD;
    float  pf = (float)pow(10000.0, e);   // correctly rounded f32 of theta^e
    float  inv = 1.0f / pf;               // f32 division like reference
    float  f = (float)pos * inv;          // single f32 rounding like reference
    c = (float)cos((double)f);
    s = (float)sin((double)f);
}

__global__ void k_rope_q() {
    int n = blockIdx.x, h = blockIdx.y, j = threadIdx.x;  // j in [0,64)
    float c, s;
    rope_cs(g_qpos[n], j, c, s);
    const float* src = g_lin + (size_t)n * H + h * HD;
    float x0 = src[j], x1 = src[j + 64];
    float* dst = g_qh + ((size_t)h * NQ + n) * HD;
    dst[j]      = x0 * c - x1 * s;
    dst[j + 64] = x1 * c + x0 * s;
}

__global__ void k_rope_k(float* __restrict__ outbuf) {
    int n = blockIdx.x, h = blockIdx.y, j = threadIdx.x;
    float c, s;
    rope_cs(g_qpos[n], j, c, s);
    const float* src = g_lin + (size_t)n * H + h * HD;
    float x0 = src[j], x1 = src[j + 64];
    float o0 = x0 * c - x1 * s;
    float o1 = x1 * c + x0 * s;
    float* dst = g_kall + ((size_t)h * NK + N_KV + n) * HD;
    dst[j] = o0; dst[j + 64] = o1;
    float* kc = outbuf + OFF_KC + ((size_t)h * S + g_hsidx[n]) * HD;
    kc[j] = o0; kc[j + 64] = o1;
}

__global__ void k_transpose_v(float* __restrict__ outbuf) {
    int n = blockIdx.x, h = blockIdx.y, d = threadIdx.x;  // d in [0,128)
    float val = g_lin[(size_t)n * H + h * HD + d];
    g_vall[((size_t)h * NK + N_KV + n) * HD + d] = val;
    outbuf[OFF_VC + ((size_t)h * S + g_hsidx[n]) * HD + d] = val;
}

__global__ void k_gather_kv(const float* __restrict__ key_cache,
                            const float* __restrict__ value_cache) {
    int kk = blockIdx.x, h = blockIdx.y, d = threadIdx.x;
    int tok = g_keytok[kk];  // kk < N_KV -> kv_idxs[kk]
    g_kall[((size_t)h * NK + kk) * HD + d] = key_cache[((size_t)h * S + tok) * HD + d];
    g_vall[((size_t)h * NK + kk) * HD + d] = value_cache[((size_t)h * S + tok) * HD + d];
}

// ---------------- masked softmax over NK (one block per (q,h)) ----------------
__global__ void k_softmax() {
    __shared__ float sh8[8];
    const int q = blockIdx.x, h = blockIdx.y;
    float* row = g_attn + ((size_t)h * NQ + q) * (size_t)NK;
    const int qp = g_qpos[q];
    const int t = threadIdx.x;
    float v[NK / 256];
    float mx = -3.4e38f;
#pragma unroll
    for (int i = 0; i < NK / 256; i++) {
        int k = i * 256 + t;
        float sc = row[k];
        if (g_kpos[k] > qp) sc += -1e9f;
        v[i] = sc;
        mx = fmaxf(mx, sc);
    }
    mx = blockMax256(mx, sh8);
    float sum = 0.f;
#pragma unroll
    for (int i = 0; i < NK / 256; i++) {
        v[i] = expf(v[i] - mx);
        sum += v[i];
    }
    sum = blockSum256(sum, sh8);
#pragma unroll
    for (int i = 0; i < NK / 256; i++) row[i * 256 + t] = v[i] / sum;
}

// ---------------- SiLU(gate) * up, in place into g_up ----------------
__global__ void k_silu(size_t n) {
    size_t i = (size_t)blockIdx.x * blockDim.x + threadIdx.x;
    if (i >= n) return;
    float x = g_gate[i];
    float sig = 1.0f / (1.0f + expf(-x));
    g_up[i] = (x * sig) * g_up[i];
}

// ---------------- prune selection ----------------
// Reference semantics decoded (validated by round-5/6 error magnitudes):
//   imp = jnp.take(attn, last_key, axis=2): last_key = N_KV+last_hs >= 2048 is
//   OOB on the Q axis (size NQ=2048) -> jnp default 'fill' mode -> imp = +NaN
//   everywhere. Then imp.at[last_key].set(inf) (in bounds on [NK]) -> one +inf.
//   -imp: +NaN negates to -NaN; the +inf becomes -inf. XLA top_k total order:
//   -NaN < -inf < finite < +inf < +NaN, so the single -inf at last_key is the
//   LARGEST element and NaNs tie stably by index. Hence
//     prune_list = [last_key, 0, 1, ..., 407]
//     to_prune_tok = {S-1} U kv_idxs[0..407]
__global__ void k_prune() {
    int i = blockIdx.x * blockDim.x + threadIdx.x;
    if (i == 0) {
        // token S-1 is always a new-idx token, never in aux_idxs
        g_pruneflag[S - 1] = 1;
    }
    if (i >= PRUNE_KN - 1) return;   // first 408 keys
    int tok = g_keytok[i];           // i < 408 < N_KV -> kv_idxs[i]
    if (!g_auxbits[tok]) g_pruneflag[tok] = 1;
}

// ---------------- aux cache scatter: aux[t] = out[map_full[t]] ----------------
__global__ void k_aux_scatter(float* __restrict__ outbuf) {
    int tpos = blockIdx.x;
    if (!g_pruneflag[tpos]) return;
    int src = g_map[tpos];   // 0 for tokens not in hs_idxs (matches reference map_full)
    const float4* s = (const float4*)(outbuf + OFF_OUT + (size_t)src * H);
    float4* d = (float4*)(outbuf + OFF_AUX + (size_t)tpos * H);
    for (int c = threadIdx.x; c < H / 4; c += blockDim.x) d[c] = s[c];
}

// ---------------- launch ----------------
extern "C" void kernel_launch(void* const* d_in, const int* in_sizes, int n_in,
                              void* d_out, int out_size) {
    (void)in_sizes; (void)n_in; (void)out_size;
    const float* hidden      = (const float*)d_in[0];
    const float* key_cache   = (const float*)d_in[1];
    const float* value_cache = (const float*)d_in[2];
    const float* aux_cache   = (const float*)d_in[3];
    const int*   kv_idxs     = (const int*)d_in[4];
    const int*   aux_idxs    = (const int*)d_in[5];
    const int*   new_idxs    = (const int*)d_in[6];
    const int*   positions   = (const int*)d_in[7];
    const float* wq     = (const float*)d_in[8];
    const float* wk     = (const float*)d_in[9];
    const float* wv     = (const float*)d_in[10];
    const float* wo     = (const float*)d_in[11];
    const float* wgate  = (const float*)d_in[12];
    const float* wup    = (const float*)d_in[13];
    const float* wdown  = (const float*)d_in[14];
    const float* ln1    = (const float*)d_in[15];
    const float* ln2    = (const float*)d_in[16];
    float* out = (float*)d_out;

    float *hs, *x, *lin, *qh, *kall, *vall, *attn, *ctx, *hs2, *gate, *up;
    cudaGetSymbolAddress((void**)&hs,   g_hs);
    cudaGetSymbolAddress((void**)&x,    g_x);
    cudaGetSymbolAddress((void**)&lin,  g_lin);
    cudaGetSymbolAddress((void**)&qh,   g_qh);
    cudaGetSymbolAddress((void**)&kall, g_kall);
    cudaGetSymbolAddress((void**)&vall, g_vall);
    cudaGetSymbolAddress((void**)&attn, g_attn);
    cudaGetSymbolAddress((void**)&ctx,  g_ctx);
    cudaGetSymbolAddress((void**)&hs2,  g_hs2);
    cudaGetSymbolAddress((void**)&gate, g_gate);
    cudaGetSymbolAddress((void**)&up,   g_up);

    const float ALPHA = 1.0f / sqrtf((float)HD);

    // indices + gathers + base copies of the three cache outputs
    k_build_idx<<<(S + 255) / 256, 256>>>(kv_idxs, aux_idxs, new_idxs, positions);
    k_scatter_idx<<<(NQ + 255) / 256, 256>>>(aux_idxs);
    k_gather_hs<<<(NQ * (H / 4) + 255) / 256, 256>>>(hidden, aux_cache);
    k_copy4<<<(int)((SZ_KC / 4 + 255) / 256), 256>>>((const float4*)key_cache,   (float4*)(out + OFF_KC), (int)(SZ_KC / 4));
    k_copy4<<<(int)((SZ_KC / 4 + 255) / 256), 256>>>((const float4*)value_cache, (float4*)(out + OFF_VC), (int)(SZ_KC / 4));
    k_copy4<<<(int)((SZ_AUX / 4 + 255) / 256), 256>>>((const float4*)aux_cache,  (float4*)(out + OFF_AUX), (int)(SZ_AUX / 4));

    // ln1
    k_rmsnorm<<<NQ, 256>>>(hs, x, ln1);

    // QKV projections (+ RoPE / transpose / cache scatter)
    sgemm128<false, false><<<dim3(H / 128, NQ / 128, 1), 256>>>(x, wq, lin, nullptr, H, H, H, H, 1.f, 0, 0, 0);
    k_rope_q<<<dim3(NQ, NH), 64>>>();
    sgemm128<false, false><<<dim3(H / 128, NQ / 128, 1), 256>>>(x, wk, lin, nullptr, H, H, H, H, 1.f, 0, 0, 0);
    k_rope_k<<<dim3(NQ, NH), 64>>>(out);
    sgemm128<false, false><<<dim3(H / 128, NQ / 128, 1), 256>>>(x, wv, lin, nullptr, H, H, H, H, 1.f, 0, 0, 0);
    k_transpose_v<<<dim3(NQ, NH), HD>>>(out);
    k_gather_kv<<<dim3(N_KV, NH), HD>>>(key_cache, value_cache);

    // attention
    sgemm128<true, false><<<dim3(NK / 128, NQ / 128, NH), 256>>>(
        qh, kall, attn, nullptr, HD, HD, HD, NK, ALPHA,
        (long long)NQ * HD, (long long)NK * HD, (long long)NQ * NK);
    k_softmax<<<dim3(NQ, NH), 256>>>();
    sgemm128<false, false><<<dim3(HD / 128, NQ / 128, NH), 256>>>(
        attn, vall, ctx, nullptr, NK, NK, HD, H, 1.f,
        (long long)NQ * NK, (long long)NK * HD, (long long)HD);

    // O-proj + residual -> hs2
    sgemm128<false, true><<<dim3(H / 128, NQ / 128, 1), 256>>>(ctx, wo, hs2, hs, H, H, H, H, 1.f, 0, 0, 0);

    // FFN
    k_rmsnorm<<<NQ, 256>>>(hs2, x, ln2);
    sgemm128<false, false><<<dim3(FF / 128, NQ / 128, 1), 256>>>(x, wgate, gate, nullptr, H, H, FF, FF, 1.f, 0, 0, 0);
    sgemm128<false, false><<<dim3(FF / 128, NQ / 128, 1), 256>>>(x, wup, up, nullptr, H, H, FF, FF, 1.f, 0, 0, 0);
    k_silu<<<(int)(((size_t)NQ * FF + 255) / 256), 256>>>((size_t)NQ * FF);
    sgemm128<false, true><<<dim3(H / 128, NQ / 128, 1), 256>>>(up, wdown, out + OFF_OUT, hs2, FF, FF, H, H, 1.f, 0, 0, 0);

    // prune selection + aux scatter (needs final out rows)
    k_prune<<<(PRUNE_KN + 255) / 256, 256>>>();
    k_aux_scatter<<<S, 256>>>(out);
}